// round 2
// baseline (speedup 1.0000x reference)
#include <cuda_runtime.h>
#include <math.h>

#define BB 2
#define SS 1024
#define DD 1024
#define HH 16
#define HD 64
#define LL 4
#define FFD 2816
#define VV 32000
#define MROWS (BB*SS)   // 2048
#define EPSV 1e-6f

// ---------------- scratch (device globals; no allocations) ----------------
__device__ float g_h  [MROWS*DD];
__device__ float g_hn [MROWS*DD];
__device__ float g_q  [MROWS*DD];
__device__ float g_k  [MROWS*DD];
__device__ float g_v  [MROWS*DD];
__device__ float g_ao [MROWS*DD];
__device__ float g_scores[(size_t)BB*HH*SS*SS];   // 134 MB
__device__ float g_f1 [MROWS*FFD];
__device__ float g_f3 [MROWS*FFD];
__device__ float g_cos[SS*(HD/2)];
__device__ float g_sin[SS*(HD/2)];

// ---------------- small elementwise kernels ----------------
__global__ void rope_tables_kernel() {
    int idx = blockIdx.x*blockDim.x + threadIdx.x;
    if (idx >= SS*(HD/2)) return;
    int s = idx / (HD/2);
    int j = idx % (HD/2);
    float inv = powf(10000.0f, -2.0f*(float)j/(float)HD);
    float ang = (float)s * inv;
    g_cos[idx] = cosf(ang);
    g_sin[idx] = sinf(ang);
}

__global__ void embed_kernel(const int* __restrict__ tokens, const float* __restrict__ emb) {
    int idx = blockIdx.x*blockDim.x + threadIdx.x;
    if (idx >= MROWS*DD) return;
    int row = idx / DD;
    int d   = idx % DD;
    g_h[idx] = emb[(size_t)tokens[row]*DD + d];
}

__global__ void rope_kernel(float* __restrict__ x) {
    int idx = blockIdx.x*blockDim.x + threadIdx.x;
    const int total = BB*SS*HH*(HD/2);
    if (idx >= total) return;
    int j = idx % (HD/2);
    int h = (idx/(HD/2)) % HH;
    int s = (idx/(HD/2)/HH) % SS;
    int b =  idx/(HD/2)/HH/SS;
    float c  = g_cos[s*(HD/2)+j];
    float sn = g_sin[s*(HD/2)+j];
    size_t base = (size_t)(b*SS+s)*DD + h*HD + 2*j;
    float x0 = x[base], x1 = x[base+1];
    x[base]   = x0*c - x1*sn;
    x[base+1] = x0*sn + x1*c;
}

__global__ void rmsnorm_kernel(const float* __restrict__ x, const float* __restrict__ w,
                               float* __restrict__ out) {
    int row = blockIdx.x;
    int t   = threadIdx.x;
    const float* xr = x + (size_t)row*DD;
    float v[4];
    float ss = 0.f;
    #pragma unroll
    for (int e = 0; e < 4; e++) { v[e] = xr[t + e*256]; ss += v[e]*v[e]; }
    __shared__ float red[256];
    red[t] = ss; __syncthreads();
    for (int off = 128; off > 0; off >>= 1) {
        if (t < off) red[t] += red[t+off];
        __syncthreads();
    }
    float scale = rsqrtf(red[0]/(float)DD + EPSV);
    #pragma unroll
    for (int e = 0; e < 4; e++) {
        int d = t + e*256;
        out[(size_t)row*DD + d] = v[e]*scale*w[d];
    }
}

__global__ void silu_mul_kernel() {
    int idx = blockIdx.x*blockDim.x + threadIdx.x;
    if (idx >= MROWS*FFD) return;
    float a = g_f1[idx];
    float sig = 1.0f / (1.0f + __expf(-a));
    g_f1[idx] = a*sig*g_f3[idx];
}

// ---------------- tiled fp32 GEMM (64x64x16, 4x4 microtile) ----------------
template<int ACC>
__global__ void gemm_nn_kernel(const float* __restrict__ A, const float* __restrict__ Bm,
                               float* __restrict__ C, int N, int K) {
    __shared__ float As[16][64];
    __shared__ float Bs[16][64];
    int tid = threadIdx.x;
    int tx = tid & 15, ty = tid >> 4;
    int m0 = blockIdx.y << 6, n0 = blockIdx.x << 6;
    float acc[4][4] = {};
    for (int k0 = 0; k0 < K; k0 += 16) {
        #pragma unroll
        for (int e = 0; e < 4; e++) {
            int lin = tid + e*256;
            int am = lin >> 4, ak = lin & 15;
            As[ak][am] = A[(size_t)(m0+am)*K + k0 + ak];
            int bk = lin >> 6, bn = lin & 63;
            Bs[bk][bn] = Bm[(size_t)(k0+bk)*N + n0 + bn];
        }
        __syncthreads();
        #pragma unroll
        for (int kk = 0; kk < 16; kk++) {
            float4 a4 = *(const float4*)&As[kk][ty*4];
            float4 b4 = *(const float4*)&Bs[kk][tx*4];
            float av[4] = {a4.x, a4.y, a4.z, a4.w};
            float bv[4] = {b4.x, b4.y, b4.z, b4.w};
            #pragma unroll
            for (int i = 0; i < 4; i++)
                #pragma unroll
                for (int j = 0; j < 4; j++)
                    acc[i][j] += av[i]*bv[j];
        }
        __syncthreads();
    }
    #pragma unroll
    for (int i = 0; i < 4; i++)
        #pragma unroll
        for (int j = 0; j < 4; j++) {
            size_t idx = (size_t)(m0 + ty*4 + i)*N + n0 + tx*4 + j;
            if (ACC) C[idx] += acc[i][j];
            else     C[idx]  = acc[i][j];
        }
}

// C[M,N] = A[M,K] * B[N,K]^T   (for logits = h @ emb^T)
__global__ void gemm_nt_kernel(const float* __restrict__ A, const float* __restrict__ Bm,
                               float* __restrict__ C, int N, int K) {
    __shared__ float As[16][64];
    __shared__ float Bs[16][64];
    int tid = threadIdx.x;
    int tx = tid & 15, ty = tid >> 4;
    int m0 = blockIdx.y << 6, n0 = blockIdx.x << 6;
    float acc[4][4] = {};
    for (int k0 = 0; k0 < K; k0 += 16) {
        #pragma unroll
        for (int e = 0; e < 4; e++) {
            int lin = tid + e*256;
            int am = lin >> 4, ak = lin & 15;
            As[ak][am] = A[(size_t)(m0+am)*K + k0 + ak];
            int bn = lin >> 4, bk = lin & 15;
            Bs[bk][bn] = Bm[(size_t)(n0+bn)*K + k0 + bk];
        }
        __syncthreads();
        #pragma unroll
        for (int kk = 0; kk < 16; kk++) {
            float4 a4 = *(const float4*)&As[kk][ty*4];
            float4 b4 = *(const float4*)&Bs[kk][tx*4];
            float av[4] = {a4.x, a4.y, a4.z, a4.w};
            float bv[4] = {b4.x, b4.y, b4.z, b4.w};
            #pragma unroll
            for (int i = 0; i < 4; i++)
                #pragma unroll
                for (int j = 0; j < 4; j++)
                    acc[i][j] += av[i]*bv[j];
        }
        __syncthreads();
    }
    #pragma unroll
    for (int i = 0; i < 4; i++)
        #pragma unroll
        for (int j = 0; j < 4; j++) {
            size_t idx = (size_t)(m0 + ty*4 + i)*N + n0 + tx*4 + j;
            C[idx] = acc[i][j];
        }
}

// ---------------- attention ----------------
// scores[b,h,i,j] = scale * q[b,i,h,:].k[b,j,h,:]  (causal mask applied)
__global__ void attn_scores_kernel() {
    int bh = blockIdx.z;
    int b = bh >> 4, h = bh & 15;
    int i0 = blockIdx.y << 6, j0 = blockIdx.x << 6;
    float* out = g_scores + (size_t)bh*SS*SS;
    int tid = threadIdx.x;
    int tx = tid & 15, ty = tid >> 4;

    if (blockIdx.x > blockIdx.y) {   // fully masked tile
        #pragma unroll
        for (int e = 0; e < 16; e++) {
            int lin = tid + e*256;
            int r = lin >> 6, c = lin & 63;
            out[(size_t)(i0+r)*SS + j0 + c] = -1e30f;
        }
        return;
    }

    __shared__ float Qs[64][65];
    __shared__ float Ks[64][65];
    #pragma unroll
    for (int e = 0; e < 16; e++) {
        int lin = tid + e*256;
        int r = lin >> 6, c = lin & 63;
        Qs[r][c] = g_q[(size_t)(b*SS + i0 + r)*DD + h*HD + c];
        Ks[r][c] = g_k[(size_t)(b*SS + j0 + r)*DD + h*HD + c];
    }
    __syncthreads();

    float acc[4][4] = {};
    #pragma unroll 8
    for (int kk = 0; kk < 64; kk++) {
        float a[4], bb[4];
        #pragma unroll
        for (int i = 0; i < 4; i++) a[i]  = Qs[ty*4+i][kk];
        #pragma unroll
        for (int j = 0; j < 4; j++) bb[j] = Ks[tx*4+j][kk];
        #pragma unroll
        for (int i = 0; i < 4; i++)
            #pragma unroll
            for (int j = 0; j < 4; j++)
                acc[i][j] += a[i]*bb[j];
    }

    const float scale = 0.125f;  // 1/sqrt(64)
    #pragma unroll
    for (int i = 0; i < 4; i++)
        #pragma unroll
        for (int j = 0; j < 4; j++) {
            int gi = i0 + ty*4 + i, gj = j0 + tx*4 + j;
            float v = acc[i][j]*scale;
            if (gj > gi) v = -1e30f;
            out[(size_t)gi*SS + gj] = v;
        }
}

__global__ void softmax_kernel() {
    int row = blockIdx.x;                 // B*H*S rows
    float* p = g_scores + (size_t)row*SS;
    int t = threadIdx.x;
    float v[4];
    float m = -1e30f;
    #pragma unroll
    for (int e = 0; e < 4; e++) { v[e] = p[t + e*256]; m = fmaxf(m, v[e]); }
    __shared__ float red[256];
    red[t] = m; __syncthreads();
    for (int off = 128; off > 0; off >>= 1) {
        if (t < off) red[t] = fmaxf(red[t], red[t+off]);
        __syncthreads();
    }
    m = red[0]; __syncthreads();
    float ssum = 0.f;
    #pragma unroll
    for (int e = 0; e < 4; e++) { v[e] = __expf(v[e]-m); ssum += v[e]; }
    red[t] = ssum; __syncthreads();
    for (int off = 128; off > 0; off >>= 1) {
        if (t < off) red[t] += red[t+off];
        __syncthreads();
    }
    float inv = 1.0f/red[0];
    #pragma unroll
    for (int e = 0; e < 4; e++) p[t + e*256] = v[e]*inv;
}

// out[b,i,h,d] = sum_j P[b,h,i,j]*v[b,j,h,d] ; causal -> only j-tiles <= i-tile
__global__ void attn_av_kernel() {
    int bh = blockIdx.z;
    int b = bh >> 4, h = bh & 15;
    int i0 = blockIdx.y << 6;
    int tid = threadIdx.x;
    int tx = tid & 15, ty = tid >> 4;
    __shared__ float Ps[64][65];
    __shared__ float Vs[64][64];
    const float* Pbase = g_scores + (size_t)bh*SS*SS;
    float acc[4][4] = {};
    for (int jt = 0; jt <= (int)blockIdx.y; jt++) {
        int j0 = jt << 6;
        #pragma unroll
        for (int e = 0; e < 16; e++) {
            int lin = tid + e*256;
            int r = lin >> 6, c = lin & 63;
            Ps[r][c] = Pbase[(size_t)(i0+r)*SS + j0 + c];
            Vs[r][c] = g_v[(size_t)(b*SS + j0 + r)*DD + h*HD + c];
        }
        __syncthreads();
        #pragma unroll 8
        for (int kk = 0; kk < 64; kk++) {
            float a[4];
            #pragma unroll
            for (int i = 0; i < 4; i++) a[i] = Ps[ty*4+i][kk];
            float4 b4 = *(const float4*)&Vs[kk][tx*4];
            float bv[4] = {b4.x, b4.y, b4.z, b4.w};
            #pragma unroll
            for (int i = 0; i < 4; i++)
                #pragma unroll
                for (int j = 0; j < 4; j++)
                    acc[i][j] += a[i]*bv[j];
        }
        __syncthreads();
    }
    #pragma unroll
    for (int i = 0; i < 4; i++)
        #pragma unroll
        for (int j = 0; j < 4; j++)
            g_ao[(size_t)(b*SS + i0 + ty*4 + i)*DD + h*HD + tx*4 + j] = acc[i][j];
}

// ---------------- host launcher ----------------
extern "C" void kernel_launch(void* const* d_in, const int* in_sizes, int n_in,
                              void* d_out, int out_size) {
    const int*   tokens     = (const int*)  d_in[0];
    const float* emb        = (const float*)d_in[1];
    const float* wq         = (const float*)d_in[2];
    const float* wk         = (const float*)d_in[3];
    const float* wv         = (const float*)d_in[4];
    const float* wo         = (const float*)d_in[5];
    const float* w1         = (const float*)d_in[6];
    const float* w2         = (const float*)d_in[7];
    const float* w3         = (const float*)d_in[8];
    const float* attn_norm  = (const float*)d_in[9];
    const float* ffn_norm   = (const float*)d_in[10];
    const float* final_norm = (const float*)d_in[11];
    float* out = (float*)d_out;
    (void)in_sizes; (void)n_in; (void)out_size;

    float *p_h, *p_hn, *p_q, *p_k, *p_v, *p_ao, *p_f1, *p_f3;
    cudaGetSymbolAddress((void**)&p_h,  g_h);
    cudaGetSymbolAddress((void**)&p_hn, g_hn);
    cudaGetSymbolAddress((void**)&p_q,  g_q);
    cudaGetSymbolAddress((void**)&p_k,  g_k);
    cudaGetSymbolAddress((void**)&p_v,  g_v);
    cudaGetSymbolAddress((void**)&p_ao, g_ao);
    cudaGetSymbolAddress((void**)&p_f1, g_f1);
    cudaGetSymbolAddress((void**)&p_f3, g_f3);

    rope_tables_kernel<<<(SS*(HD/2)+255)/256, 256>>>();
    embed_kernel<<<(MROWS*DD+255)/256, 256>>>(tokens, emb);

    for (int l = 0; l < LL; l++) {
        // attention block
        rmsnorm_kernel<<<MROWS, 256>>>(p_h, attn_norm + l*DD, p_hn);
        gemm_nn_kernel<0><<<dim3(DD/64, MROWS/64), 256>>>(p_hn, wq + (size_t)l*DD*DD, p_q, DD, DD);
        gemm_nn_kernel<0><<<dim3(DD/64, MROWS/64), 256>>>(p_hn, wk + (size_t)l*DD*DD, p_k, DD, DD);
        gemm_nn_kernel<0><<<dim3(DD/64, MROWS/64), 256>>>(p_hn, wv + (size_t)l*DD*DD, p_v, DD, DD);
        rope_kernel<<<(BB*SS*HH*(HD/2)+255)/256, 256>>>(p_q);
        rope_kernel<<<(BB*SS*HH*(HD/2)+255)/256, 256>>>(p_k);
        attn_scores_kernel<<<dim3(SS/64, SS/64, BB*HH), 256>>>();
        softmax_kernel<<<BB*HH*SS, 256>>>();
        attn_av_kernel<<<dim3(1, SS/64, BB*HH), 256>>>();
        gemm_nn_kernel<1><<<dim3(DD/64, MROWS/64), 256>>>(p_ao, wo + (size_t)l*DD*DD, p_h, DD, DD);

        // FFN block
        rmsnorm_kernel<<<MROWS, 256>>>(p_h, ffn_norm + l*DD, p_hn);
        gemm_nn_kernel<0><<<dim3(FFD/64, MROWS/64), 256>>>(p_hn, w1 + (size_t)l*DD*FFD, p_f1, FFD, DD);
        gemm_nn_kernel<0><<<dim3(FFD/64, MROWS/64), 256>>>(p_hn, w3 + (size_t)l*DD*FFD, p_f3, FFD, DD);
        silu_mul_kernel<<<(MROWS*FFD+255)/256, 256>>>();
        gemm_nn_kernel<1><<<dim3(DD/64, MROWS/64), 256>>>(p_f1, w2 + (size_t)l*FFD*DD, p_h, DD, FFD);
    }

    rmsnorm_kernel<<<MROWS, 256>>>(p_h, final_norm, p_hn);
    gemm_nt_kernel<<<dim3(VV/64, MROWS/64), 256>>>(p_hn, emb, out, VV, DD);
}

// round 7
// speedup vs baseline: 2.8437x; 2.8437x over previous
#include <cuda_runtime.h>
#include <math.h>

#define BB 2
#define SS 1024
#define DD 1024
#define HH 16
#define HD 64
#define LL 4
#define FFD 2816
#define VV 32000
#define MROWS (BB*SS)   // 2048
#define EPSV 1e-6f

// ---------------- scratch (device globals; no allocations) ----------------
__device__ float g_h  [MROWS*DD];
__device__ float g_hn [MROWS*DD];
__device__ float g_q  [MROWS*DD];
__device__ float g_k  [MROWS*DD];
__device__ float g_v  [MROWS*DD];
__device__ float g_ao [MROWS*DD];
__device__ float g_scores[(size_t)BB*HH*SS*SS];   // 134 MB
__device__ float g_f1 [MROWS*FFD];
__device__ float g_f3 [MROWS*FFD];
__device__ float g_cos[SS*(HD/2)];
__device__ float g_sin[SS*(HD/2)];

// ---------------- small elementwise kernels ----------------
__global__ void rope_tables_kernel() {
    int idx = blockIdx.x*blockDim.x + threadIdx.x;
    if (idx >= SS*(HD/2)) return;
    int s = idx / (HD/2);
    int j = idx % (HD/2);
    float inv = powf(10000.0f, -2.0f*(float)j/(float)HD);
    float ang = (float)s * inv;
    g_cos[idx] = cosf(ang);
    g_sin[idx] = sinf(ang);
}

__global__ void embed_kernel(const int* __restrict__ tokens, const float* __restrict__ emb) {
    int idx = blockIdx.x*blockDim.x + threadIdx.x;
    if (idx >= MROWS*DD) return;
    int row = idx / DD;
    int d   = idx % DD;
    g_h[idx] = emb[(size_t)tokens[row]*DD + d];
}

__global__ void rope_kernel(float* __restrict__ x) {
    int idx = blockIdx.x*blockDim.x + threadIdx.x;
    const int total = BB*SS*HH*(HD/2);
    if (idx >= total) return;
    int j = idx % (HD/2);
    int h = (idx/(HD/2)) % HH;
    int s = (idx/(HD/2)/HH) % SS;
    int b =  idx/(HD/2)/HH/SS;
    float c  = g_cos[s*(HD/2)+j];
    float sn = g_sin[s*(HD/2)+j];
    size_t base = (size_t)(b*SS+s)*DD + h*HD + 2*j;
    float x0 = x[base], x1 = x[base+1];
    x[base]   = x0*c - x1*sn;
    x[base+1] = x0*sn + x1*c;
}

__global__ void rmsnorm_kernel(const float* __restrict__ x, const float* __restrict__ w,
                               float* __restrict__ out) {
    int row = blockIdx.x;
    int t   = threadIdx.x;
    const float* xr = x + (size_t)row*DD;
    float v[4];
    float ss = 0.f;
    #pragma unroll
    for (int e = 0; e < 4; e++) { v[e] = xr[t + e*256]; ss += v[e]*v[e]; }
    __shared__ float red[256];
    red[t] = ss; __syncthreads();
    for (int off = 128; off > 0; off >>= 1) {
        if (t < off) red[t] += red[t+off];
        __syncthreads();
    }
    float scale = rsqrtf(red[0]/(float)DD + EPSV);
    #pragma unroll
    for (int e = 0; e < 4; e++) {
        int d = t + e*256;
        out[(size_t)row*DD + d] = v[e]*scale*w[d];
    }
}

__global__ void silu_mul_kernel() {
    int idx = blockIdx.x*blockDim.x + threadIdx.x;
    if (idx >= MROWS*FFD) return;
    float a = g_f1[idx];
    float sig = 1.0f / (1.0f + __expf(-a));
    g_f1[idx] = a*sig*g_f3[idx];
}

// ---------------- 3xTF32 tensor-core GEMM (fp32 accuracy) ----------------
// C[M,N] = A[M,K] @ op(B);  TRANSB=0: B[K,N];  TRANSB=1: B[N,K] (C = A @ B^T)
// Block tile 128x128, K-chunk 16, 8 warps in 4(m) x 2(n), warp tile 32x64.
// Each fp32 operand is split a = hi + lo (both TF32); acc gets
// a_lo*b_hi + a_hi*b_lo + a_hi*b_hi  -> ~fp32-accurate product.

__device__ __forceinline__ unsigned f2tf(float f) {
    unsigned u;
    asm("cvt.rna.tf32.f32 %0, %1;" : "=r"(u) : "f"(f));
    return u;
}

__device__ __forceinline__ void split_tf(float f, unsigned& hi, unsigned& lo) {
    hi = f2tf(f);
    lo = f2tf(f - __uint_as_float(hi));
}

__device__ __forceinline__ void mma_tf32(float* c, const unsigned* a, const unsigned* b) {
    asm volatile(
        "mma.sync.aligned.m16n8k8.row.col.f32.tf32.tf32.f32 "
        "{%0,%1,%2,%3}, {%4,%5,%6,%7}, {%8,%9}, {%0,%1,%2,%3};\n"
        : "+f"(c[0]), "+f"(c[1]), "+f"(c[2]), "+f"(c[3])
        : "r"(a[0]), "r"(a[1]), "r"(a[2]), "r"(a[3]), "r"(b[0]), "r"(b[1]));
}

#define PADW 136

template<int TRANSB, int ACC>
__global__ void gemm_tf32x3_kernel(const float* __restrict__ A, const float* __restrict__ B,
                                   float* __restrict__ C, int M, int N, int K) {
    __shared__ float As[2][16][PADW];   // [k][m], raw fp32
    __shared__ float Bs[2][16][PADW];   // [k][n], raw fp32

    int tid  = threadIdx.x;
    int lane = tid & 31;
    int gr   = lane >> 2;     // 0..7
    int tg   = lane & 3;      // 0..3
    int wid  = tid >> 5;      // 0..7
    int wm   = (wid >> 1) * 32;
    int wn   = (wid & 1) * 64;
    int m0   = blockIdx.y << 7;
    int n0   = blockIdx.x << 7;

    float acc[2][8][4];
    #pragma unroll
    for (int mi = 0; mi < 2; mi++)
        #pragma unroll
        for (int ni = 0; ni < 8; ni++)
            #pragma unroll
            for (int r = 0; r < 4; r++) acc[mi][ni][r] = 0.f;

    const int nk = K >> 4;

    // ---- prologue: load chunk 0 into buffer 0 ----
    {
        #pragma unroll
        for (int e = 0; e < 2; e++) {
            int idx = tid + e*256;
            int row = idx >> 2;              // 0..127 (m)
            int kq  = (idx & 3) << 2;        // 0,4,8,12
            float4 a4 = *(const float4*)&A[(size_t)(m0+row)*K + kq];
            As[0][kq+0][row] = a4.x;
            As[0][kq+1][row] = a4.y;
            As[0][kq+2][row] = a4.z;
            As[0][kq+3][row] = a4.w;
        }
        if (!TRANSB) {
            #pragma unroll
            for (int e = 0; e < 2; e++) {
                int idx = tid + e*256;
                int k  = idx >> 5;           // 0..15
                int nq = (idx & 31) << 2;    // 0..124
                float4 b4 = *(const float4*)&B[(size_t)k*N + n0 + nq];
                *(float4*)&Bs[0][k][nq] = b4;
            }
        } else {
            #pragma unroll
            for (int e = 0; e < 2; e++) {
                int idx = tid + e*256;
                int row = idx >> 2;          // n, 0..127
                int kq  = (idx & 3) << 2;
                float4 b4 = *(const float4*)&B[(size_t)(n0+row)*K + kq];
                Bs[0][kq+0][row] = b4.x;
                Bs[0][kq+1][row] = b4.y;
                Bs[0][kq+2][row] = b4.z;
                Bs[0][kq+3][row] = b4.w;
            }
        }
    }
    __syncthreads();

    for (int kc = 0; kc < nk; kc++) {
        int buf = kc & 1;
        // ---- prefetch next chunk into other buffer ----
        if (kc + 1 < nk) {
            int k0 = (kc + 1) << 4;
            int nb = buf ^ 1;
            #pragma unroll
            for (int e = 0; e < 2; e++) {
                int idx = tid + e*256;
                int row = idx >> 2;
                int kq  = (idx & 3) << 2;
                float4 a4 = *(const float4*)&A[(size_t)(m0+row)*K + k0 + kq];
                As[nb][kq+0][row] = a4.x;
                As[nb][kq+1][row] = a4.y;
                As[nb][kq+2][row] = a4.z;
                As[nb][kq+3][row] = a4.w;
            }
            if (!TRANSB) {
                #pragma unroll
                for (int e = 0; e < 2; e++) {
                    int idx = tid + e*256;
                    int k  = idx >> 5;
                    int nq = (idx & 31) << 2;
                    float4 b4 = *(const float4*)&B[(size_t)(k0+k)*N + n0 + nq];
                    *(float4*)&Bs[nb][k][nq] = b4;
                }
            } else {
                #pragma unroll
                for (int e = 0; e < 2; e++) {
                    int idx = tid + e*256;
                    int row = idx >> 2;
                    int kq  = (idx & 3) << 2;
                    float4 b4 = *(const float4*)&B[(size_t)(n0+row)*K + k0 + kq];
                    Bs[nb][kq+0][row] = b4.x;
                    Bs[nb][kq+1][row] = b4.y;
                    Bs[nb][kq+2][row] = b4.z;
                    Bs[nb][kq+3][row] = b4.w;
                }
            }
        }

        // ---- compute on current buffer ----
        #pragma unroll
        for (int ks = 0; ks < 2; ks++) {
            int kb = ks << 3;
            unsigned ah[2][4], al[2][4], bh[8][2], bl[8][2];
            #pragma unroll
            for (int mi = 0; mi < 2; mi++) {
                int mb = wm + mi*16;
                split_tf(As[buf][kb+tg  ][mb+gr  ], ah[mi][0], al[mi][0]);
                split_tf(As[buf][kb+tg  ][mb+gr+8], ah[mi][1], al[mi][1]);
                split_tf(As[buf][kb+tg+4][mb+gr  ], ah[mi][2], al[mi][2]);
                split_tf(As[buf][kb+tg+4][mb+gr+8], ah[mi][3], al[mi][3]);
            }
            #pragma unroll
            for (int ni = 0; ni < 8; ni++) {
                int nb2 = wn + ni*8 + gr;
                split_tf(Bs[buf][kb+tg  ][nb2], bh[ni][0], bl[ni][0]);
                split_tf(Bs[buf][kb+tg+4][nb2], bh[ni][1], bl[ni][1]);
            }
            #pragma unroll
            for (int mi = 0; mi < 2; mi++)
                #pragma unroll
                for (int ni = 0; ni < 8; ni++) {
                    mma_tf32(acc[mi][ni], al[mi], bh[ni]);
                    mma_tf32(acc[mi][ni], ah[mi], bl[ni]);
                    mma_tf32(acc[mi][ni], ah[mi], bh[ni]);
                }
        }
        __syncthreads();
    }

    // ---- epilogue ----
    #pragma unroll
    for (int mi = 0; mi < 2; mi++) {
        int r0 = m0 + wm + mi*16 + gr;
        #pragma unroll
        for (int ni = 0; ni < 8; ni++) {
            int c0 = n0 + wn + ni*8 + tg*2;
            float* p0 = &C[(size_t)r0*N + c0];
            float* p1 = &C[(size_t)(r0+8)*N + c0];
            if (ACC) {
                p0[0] += acc[mi][ni][0]; p0[1] += acc[mi][ni][1];
                p1[0] += acc[mi][ni][2]; p1[1] += acc[mi][ni][3];
            } else {
                p0[0] = acc[mi][ni][0]; p0[1] = acc[mi][ni][1];
                p1[0] = acc[mi][ni][2]; p1[1] = acc[mi][ni][3];
            }
        }
    }
}

// ---------------- attention ----------------
__global__ void attn_scores_kernel() {
    int bh = blockIdx.z;
    int b = bh >> 4, h = bh & 15;
    int i0 = blockIdx.y << 6, j0 = blockIdx.x << 6;
    float* out = g_scores + (size_t)bh*SS*SS;
    int tid = threadIdx.x;
    int tx = tid & 15, ty = tid >> 4;

    if (blockIdx.x > blockIdx.y) {   // fully masked tile
        #pragma unroll
        for (int e = 0; e < 16; e++) {
            int lin = tid + e*256;
            int r = lin >> 6, c = lin & 63;
            out[(size_t)(i0+r)*SS + j0 + c] = -1e30f;
        }
        return;
    }

    __shared__ float Qs[64][65];
    __shared__ float Ks[64][65];
    #pragma unroll
    for (int e = 0; e < 16; e++) {
        int lin = tid + e*256;
        int r = lin >> 6, c = lin & 63;
        Qs[r][c] = g_q[(size_t)(b*SS + i0 + r)*DD + h*HD + c];
        Ks[r][c] = g_k[(size_t)(b*SS + j0 + r)*DD + h*HD + c];
    }
    __syncthreads();

    float acc[4][4] = {};
    #pragma unroll 8
    for (int kk = 0; kk < 64; kk++) {
        float a[4], bb[4];
        #pragma unroll
        for (int i = 0; i < 4; i++) a[i]  = Qs[ty*4+i][kk];
        #pragma unroll
        for (int j = 0; j < 4; j++) bb[j] = Ks[tx*4+j][kk];
        #pragma unroll
        for (int i = 0; i < 4; i++)
            #pragma unroll
            for (int j = 0; j < 4; j++)
                acc[i][j] += a[i]*bb[j];
    }

    const float scale = 0.125f;
    #pragma unroll
    for (int i = 0; i < 4; i++)
        #pragma unroll
        for (int j = 0; j < 4; j++) {
            int gi = i0 + ty*4 + i, gj = j0 + tx*4 + j;
            float v = acc[i][j]*scale;
            if (gj > gi) v = -1e30f;
            out[(size_t)gi*SS + gj] = v;
        }
}

__global__ void softmax_kernel() {
    int row = blockIdx.x;
    float* p = g_scores + (size_t)row*SS;
    int t = threadIdx.x;
    float v[4];
    float m = -1e30f;
    #pragma unroll
    for (int e = 0; e < 4; e++) { v[e] = p[t + e*256]; m = fmaxf(m, v[e]); }
    __shared__ float red[256];
    red[t] = m; __syncthreads();
    for (int off = 128; off > 0; off >>= 1) {
        if (t < off) red[t] = fmaxf(red[t], red[t+off]);
        __syncthreads();
    }
    m = red[0]; __syncthreads();
    float ssum = 0.f;
    #pragma unroll
    for (int e = 0; e < 4; e++) { v[e] = __expf(v[e]-m); ssum += v[e]; }
    red[t] = ssum; __syncthreads();
    for (int off = 128; off > 0; off >>= 1) {
        if (t < off) red[t] += red[t+off];
        __syncthreads();
    }
    float inv = 1.0f/red[0];
    #pragma unroll
    for (int e = 0; e < 4; e++) p[t + e*256] = v[e]*inv;
}

__global__ void attn_av_kernel() {
    int bh = blockIdx.z;
    int b = bh >> 4, h = bh & 15;
    int i0 = blockIdx.y << 6;
    int tid = threadIdx.x;
    int tx = tid & 15, ty = tid >> 4;
    __shared__ float Ps[64][65];
    __shared__ float Vs[64][64];
    const float* Pbase = g_scores + (size_t)bh*SS*SS;
    float acc[4][4] = {};
    for (int jt = 0; jt <= (int)blockIdx.y; jt++) {
        int j0 = jt << 6;
        #pragma unroll
        for (int e = 0; e < 16; e++) {
            int lin = tid + e*256;
            int r = lin >> 6, c = lin & 63;
            Ps[r][c] = Pbase[(size_t)(i0+r)*SS + j0 + c];
            Vs[r][c] = g_v[(size_t)(b*SS + j0 + r)*DD + h*HD + c];
        }
        __syncthreads();
        #pragma unroll 8
        for (int kk = 0; kk < 64; kk++) {
            float a[4];
            #pragma unroll
            for (int i = 0; i < 4; i++) a[i] = Ps[ty*4+i][kk];
            float4 b4 = *(const float4*)&Vs[kk][tx*4];
            float bv[4] = {b4.x, b4.y, b4.z, b4.w};
            #pragma unroll
            for (int i = 0; i < 4; i++)
                #pragma unroll
                for (int j = 0; j < 4; j++)
                    acc[i][j] += a[i]*bv[j];
        }
        __syncthreads();
    }
    #pragma unroll
    for (int i = 0; i < 4; i++)
        #pragma unroll
        for (int j = 0; j < 4; j++)
            g_ao[(size_t)(b*SS + i0 + ty*4 + i)*DD + h*HD + tx*4 + j] = acc[i][j];
}

// ---------------- host launcher ----------------
extern "C" void kernel_launch(void* const* d_in, const int* in_sizes, int n_in,
                              void* d_out, int out_size) {
    const int*   tokens     = (const int*)  d_in[0];
    const float* emb        = (const float*)d_in[1];
    const float* wq         = (const float*)d_in[2];
    const float* wk         = (const float*)d_in[3];
    const float* wv         = (const float*)d_in[4];
    const float* wo         = (const float*)d_in[5];
    const float* w1         = (const float*)d_in[6];
    const float* w2         = (const float*)d_in[7];
    const float* w3         = (const float*)d_in[8];
    const float* attn_norm  = (const float*)d_in[9];
    const float* ffn_norm   = (const float*)d_in[10];
    const float* final_norm = (const float*)d_in[11];
    float* out = (float*)d_out;
    (void)in_sizes; (void)n_in; (void)out_size;

    float *p_h, *p_hn, *p_q, *p_k, *p_v, *p_ao, *p_f1, *p_f3;
    cudaGetSymbolAddress((void**)&p_h,  g_h);
    cudaGetSymbolAddress((void**)&p_hn, g_hn);
    cudaGetSymbolAddress((void**)&p_q,  g_q);
    cudaGetSymbolAddress((void**)&p_k,  g_k);
    cudaGetSymbolAddress((void**)&p_v,  g_v);
    cudaGetSymbolAddress((void**)&p_ao, g_ao);
    cudaGetSymbolAddress((void**)&p_f1, g_f1);
    cudaGetSymbolAddress((void**)&p_f3, g_f3);

    rope_tables_kernel<<<(SS*(HD/2)+255)/256, 256>>>();
    embed_kernel<<<(MROWS*DD+255)/256, 256>>>(tokens, emb);

    for (int l = 0; l < LL; l++) {
        // attention block
        rmsnorm_kernel<<<MROWS, 256>>>(p_h, attn_norm + l*DD, p_hn);
        gemm_tf32x3_kernel<0,0><<<dim3(DD/128, MROWS/128), 256>>>(p_hn, wq + (size_t)l*DD*DD, p_q, MROWS, DD, DD);
        gemm_tf32x3_kernel<0,0><<<dim3(DD/128, MROWS/128), 256>>>(p_hn, wk + (size_t)l*DD*DD, p_k, MROWS, DD, DD);
        gemm_tf32x3_kernel<0,0><<<dim3(DD/128, MROWS/128), 256>>>(p_hn, wv + (size_t)l*DD*DD, p_v, MROWS, DD, DD);
        rope_kernel<<<(BB*SS*HH*(HD/2)+255)/256, 256>>>(p_q);
        rope_kernel<<<(BB*SS*HH*(HD/2)+255)/256, 256>>>(p_k);
        attn_scores_kernel<<<dim3(SS/64, SS/64, BB*HH), 256>>>();
        softmax_kernel<<<BB*HH*SS, 256>>>();
        attn_av_kernel<<<dim3(1, SS/64, BB*HH), 256>>>();
        gemm_tf32x3_kernel<0,1><<<dim3(DD/128, MROWS/128), 256>>>(p_ao, wo + (size_t)l*DD*DD, p_h, MROWS, DD, DD);

        // FFN block
        rmsnorm_kernel<<<MROWS, 256>>>(p_h, ffn_norm + l*DD, p_hn);
        gemm_tf32x3_kernel<0,0><<<dim3(FFD/128, MROWS/128), 256>>>(p_hn, w1 + (size_t)l*DD*FFD, p_f1, MROWS, FFD, DD);
        gemm_tf32x3_kernel<0,0><<<dim3(FFD/128, MROWS/128), 256>>>(p_hn, w3 + (size_t)l*DD*FFD, p_f3, MROWS, FFD, DD);
        silu_mul_kernel<<<(MROWS*FFD+255)/256, 256>>>();
        gemm_tf32x3_kernel<0,1><<<dim3(DD/128, MROWS/128), 256>>>(p_f1, w2 + (size_t)l*FFD*DD, p_h, MROWS, DD, FFD);
    }

    rmsnorm_kernel<<<MROWS, 256>>>(p_h, final_norm, p_hn);
    gemm_tf32x3_kernel<1,0><<<dim3(VV/128, MROWS/128), 256>>>(p_hn, emb, out, MROWS, VV, DD);
}